// round 13
// baseline (speedup 1.0000x reference)
#include <cuda_runtime.h>
#include <cstdint>

#define BATCH        262144
#define IN_DIM       64
#define LAT          512
#define KSEL         32
#define NWARPS       8          // 256 threads
#define ROWS_PER_CTA 32
#define NBIN         512
#define SHIFT        21
#define CHUNK_K      16
#define NCHUNK       (IN_DIM / CHUNK_K)

typedef unsigned int       u32;
typedef unsigned long long u64;

// Transposed weights (prep kernel fills these each launch; tiny cost).
__device__ __align__(16) float g_encWT[IN_DIM * LAT];   // [k][j]
__device__ __align__(16) float g_decWT[LAT * IN_DIM];   // [j][i]
// Fallback sink if the harness only scores one of the two outputs.
__device__ float g_scratch[(size_t)BATCH * LAT];

// ---------------- packed f32x2 helpers ----------------
__device__ __forceinline__ u64 pack2(float x) {
    u64 r;
    asm("mov.b64 %0, {%1, %1};" : "=l"(r) : "r"(__float_as_uint(x)));
    return r;
}
__device__ __forceinline__ void fma2(u64& d, u64 a, u64 b) {
    asm("fma.rn.f32x2 %0, %1, %2, %0;" : "+l"(d) : "l"(a), "l"(b));
}
__device__ __forceinline__ u64 add2(u64 a, u64 b) {
    u64 r;
    asm("add.rn.f32x2 %0, %1, %2;" : "=l"(r) : "l"(a), "l"(b));
    return r;
}
__device__ __forceinline__ float2 unpack2(u64 v) {
    float2 f;
    asm("mov.b64 {%0, %1}, %2;" : "=f"(f.x), "=f"(f.y) : "l"(v));
    return f;
}

// ---------------- prep: transpose both weight matrices ----------------
__global__ void prep_transpose(const float* __restrict__ encW,   // [LAT][IN_DIM]
                               const float* __restrict__ decW) { // [IN_DIM][LAT]
    int idx = blockIdx.x * blockDim.x + threadIdx.x;
    if (idx < LAT * IN_DIM) {
        int j = idx / IN_DIM, k = idx - j * IN_DIM;
        g_encWT[k * LAT + j] = encW[idx];
        int i2 = idx / LAT, j2 = idx - i2 * LAT;
        g_decWT[j2 * IN_DIM + i2] = decW[idx];
    }
}

// ---------------- dynamic smem layout (u32 words) ----------------
// region A (32 KB): weight chunks during encoder, half-exchange buffer afterwards
#define OFF_A      0                                   // 8192 u32
#define OFF_X      8192                                // 32*64 floats  = 8 KB
#define OFF_HIST   (OFF_X + ROWS_PER_CTA * IN_DIM)     // 8 warps * 256 u32 (packed u16x2) = 8 KB
#define OFF_CAND   (OFF_HIST + NWARPS * (NBIN / 2))    // 8 warps * 32 u32 = 1 KB
#define OFF_SEL    (OFF_CAND + NWARPS * 32)            // 8 warps * 32 u64 = 2 KB
#define OFF_CNT    (OFF_SEL + NWARPS * KSEL * 2)       // 8
#define SMEM_WORDS (OFF_CNT + NWARPS)
#define SMEM_BYTES (SMEM_WORDS * 4)

// ---------------- fused encoder + exact top-k + sparse decoder ----------------
__global__ __launch_bounds__(256, 2)
void sae_fused(const float* __restrict__ x,
               const float* __restrict__ enc_b,
               const float* __restrict__ dec_b,
               float* out_x_in,      // [B][64]  (may be null)
               float* out_z_in)      // [B][512] (may be null)
{
    extern __shared__ u32 sm[];
    float* s_w   = (float*)(sm + OFF_A);      // encoder phase
    u32*   s_ex  = sm + OFF_A;                // exchange phase (same region)
    float* s_x   = (float*)(sm + OFF_X);
    u32*   s_hist= sm + OFF_HIST;
    u32*   s_cand= sm + OFF_CAND;
    u64*   s_sel = (u64*)(sm + OFF_SEL);
    u32*   s_cnt = sm + OFF_CNT;

    float* out_x = out_x_in ? out_x_in : g_scratch;
    float* out_z = out_z_in ? out_z_in : g_scratch;

    const int tid  = threadIdx.x;
    const int warp = tid >> 5;
    const int lane = tid & 31;
    const int h    = warp & 1;          // latent half
    const int g    = warp >> 1;         // row group (8 rows)
    const size_t rowBase = (size_t)blockIdx.x * ROWS_PER_CTA;

    // ---- stage x tile (32 rows x 64 = 512 float4), streaming loads ----
    {
        const float4* xs = (const float4*)(x + rowBase * IN_DIM);
        float4* xd = (float4*)s_x;
        xd[tid]       = __ldcs(xs + tid);
        xd[tid + 256] = __ldcs(xs + tid + 256);
    }

    // ---- encoder: warp owns 8 rows (8g..8g+7) x 256 latents (half h).
    // lane owns latents l = 128t + 4*lane + (2p+e), acc[r][2t+p] = f32x2 latent pair.
    u64 acc[8][4];
    {
        const float4 b4a = *(const float4*)(enc_b + 256 * h + 4 * lane);
        const float4 b4b = *(const float4*)(enc_b + 256 * h + 128 + 4 * lane);
        u64 b0 = pack2(b4a.x) , b1 = pack2(b4a.z);
        u64 b2 = pack2(b4b.x) , b3 = pack2(b4b.z);
        // NOTE: pairs are (l, l+1): acc[r][2t+p] covers latents 128t+4lane+2p, +1
        u64 p00 = pack2(b4a.x), p01 = pack2(b4a.z), p10 = pack2(b4b.x), p11 = pack2(b4b.z);
        // but each f32x2 lane half must hold the bias of ITS latent:
        // latent pair (j, j+1) -> (bias[j], bias[j+1])
        u64 q00, q01, q10, q11;
        asm("mov.b64 %0, {%1, %2};" : "=l"(q00) : "r"(__float_as_uint(b4a.x)), "r"(__float_as_uint(b4a.y)));
        asm("mov.b64 %0, {%1, %2};" : "=l"(q01) : "r"(__float_as_uint(b4a.z)), "r"(__float_as_uint(b4a.w)));
        asm("mov.b64 %0, {%1, %2};" : "=l"(q10) : "r"(__float_as_uint(b4b.x)), "r"(__float_as_uint(b4b.y)));
        asm("mov.b64 %0, {%1, %2};" : "=l"(q11) : "r"(__float_as_uint(b4b.z)), "r"(__float_as_uint(b4b.w)));
        (void)b0;(void)b1;(void)b2;(void)b3;(void)p00;(void)p01;(void)p10;(void)p11;
#pragma unroll
        for (int r = 0; r < 8; ++r) {
            acc[r][0] = q00; acc[r][1] = q01; acc[r][2] = q10; acc[r][3] = q11;
        }
    }

    const float* xw = s_x + (8 * g) * IN_DIM;

    for (int c = 0; c < NCHUNK; ++c) {
        __syncthreads();   // previous chunk fully consumed (and x staged, first iter)
        {
            const float4* wsrc = (const float4*)(g_encWT + c * CHUNK_K * LAT);
            float4* wdst = (float4*)s_w;
#pragma unroll
            for (int i = 0; i < 8; ++i) wdst[tid + i * 256] = __ldcg(wsrc + tid + i * 256);
        }
        __syncthreads();

#pragma unroll
        for (int kq = 0; kq < CHUNK_K / 4; ++kq) {
            float4 xq[8];
#pragma unroll
            for (int r = 0; r < 8; ++r)
                xq[r] = *(const float4*)(xw + r * IN_DIM + c * CHUNK_K + kq * 4);

#pragma unroll
            for (int kk = 0; kk < 4; ++kk) {
                const int ksm = kq * 4 + kk;
                u64 xp[8];
#pragma unroll
                for (int r = 0; r < 8; ++r)
                    xp[r] = pack2(((const float*)&xq[r])[kk]);
                ulonglong2 w0 = *(const ulonglong2*)(s_w + ksm * LAT + 256 * h +       4 * lane);
                ulonglong2 w1 = *(const ulonglong2*)(s_w + ksm * LAT + 256 * h + 128 + 4 * lane);
#pragma unroll
                for (int r = 0; r < 8; ++r) {
                    fma2(acc[r][0], xp[r], w0.x);
                    fma2(acc[r][1], xp[r], w0.y);
                    fma2(acc[r][2], xp[r], w1.x);
                    fma2(acc[r][3], xp[r], w1.y);
                }
            }
        }
    }
    __syncthreads();   // all warps done with s_w -> safe to overlay exchange buffer

    // ---- half-exchange: warp w gives partner (w^1) its half of partner's topk rows.
    // topk rows of warp w = 8g + 4h .. +3  (acc indices 4h..4h+3)
    // so warp w WRITES acc rows 4*(1-h)..+3 into buffer slot of partner.
    {
        const int pw = warp ^ 1;
#pragma unroll
        for (int rr = 0; rr < 4; ++rr) {
            const int r = 4 * (1 - h) + rr;
            float2 f0 = unpack2(acc[r][0]), f1 = unpack2(acc[r][1]);
            float2 f2 = unpack2(acc[r][2]), f3 = unpack2(acc[r][3]);
            uint4 a, b;
            a.x = (f0.x > 0.f) ? __float_as_uint(f0.x) : 0u;
            a.y = (f0.y > 0.f) ? __float_as_uint(f0.y) : 0u;
            a.z = (f1.x > 0.f) ? __float_as_uint(f1.x) : 0u;
            a.w = (f1.y > 0.f) ? __float_as_uint(f1.y) : 0u;
            b.x = (f2.x > 0.f) ? __float_as_uint(f2.x) : 0u;
            b.y = (f2.y > 0.f) ? __float_as_uint(f2.y) : 0u;
            b.z = (f3.x > 0.f) ? __float_as_uint(f3.x) : 0u;
            b.w = (f3.y > 0.f) ? __float_as_uint(f3.y) : 0u;
            *(uint4*)(s_ex + pw * 1024 + rr * 256 +       4 * lane) = a;
            *(uint4*)(s_ex + pw * 1024 + rr * 256 + 128 + 4 * lane) = b;
        }
    }
    __syncthreads();

    const u64 dbias = *(const u64*)(dec_b + 2 * lane);
    u32* hist = s_hist + warp * (NBIN / 2);
    u32* cand = s_cand + warp * 32;
    u64* sel  = s_sel  + warp * KSEL;

    // slot -> latent index (s<8: own half from acc; s>=8: partner half from smem)
    auto jmap = [&](int s) -> int {
        int half = (s < 8) ? h : (1 - h);
        return 256 * half + 128 * ((s >> 2) & 1) + 4 * lane + (s & 3);
    };

    // ---- per-row: relu -> exact top-32 (radix select on float bits) -> writes ----
    for (int rr = 0; rr < 4; ++rr) {
        const int    r   = 4 * h + rr;               // acc index of this topk row
        const size_t row = rowBase + 8 * g + 4 * h + rr;

        u32 zb[16];
#pragma unroll
        for (int i = 0; i < 4; ++i) {
            float2 f = unpack2(acc[r][i]);
            zb[2 * i]     = (f.x > 0.f) ? __float_as_uint(f.x) : 0u;
            zb[2 * i + 1] = (f.y > 0.f) ? __float_as_uint(f.y) : 0u;
        }
        {
            uint4 a = *(const uint4*)(s_ex + warp * 1024 + rr * 256 +       4 * lane);
            uint4 b = *(const uint4*)(s_ex + warp * 1024 + rr * 256 + 128 + 4 * lane);
            zb[8] = a.x; zb[9] = a.y; zb[10] = a.z; zb[11] = a.w;
            zb[12] = b.x; zb[13] = b.y; zb[14] = b.z; zb[15] = b.w;
        }

        // 512-bin histogram on bits[30:21], packed 2 bins/u32 (u16 counts); skip zeros
        {
            uint4 z4 = make_uint4(0u, 0u, 0u, 0u);
            ((uint4*)hist)[lane * 2]     = z4;
            ((uint4*)hist)[lane * 2 + 1] = z4;
        }
        __syncwarp();
#pragma unroll
        for (int s = 0; s < 16; ++s)
            if (zb[s]) {
                u32 b = min(zb[s] >> SHIFT, (u32)(NBIN - 1));
                atomicAdd(&hist[b >> 1], 1u << ((b & 1) * 16));
            }
        __syncwarp();

        // lane owns bins [16*lane, 16*lane+16) = words [8*lane, 8*lane+8)
        u32 h16[16];
        {
            uint4 wa = ((const uint4*)hist)[lane * 2];
            uint4 wb = ((const uint4*)hist)[lane * 2 + 1];
            u32 wsv[8] = {wa.x, wa.y, wa.z, wa.w, wb.x, wb.y, wb.z, wb.w};
#pragma unroll
            for (int i = 0; i < 8; ++i) {
                h16[2 * i]     = wsv[i] & 0xffffu;
                h16[2 * i + 1] = wsv[i] >> 16;
            }
        }
        u32 suf[16];
        suf[15] = h16[15];
#pragma unroll
        for (int i = 14; i >= 0; --i) suf[i] = suf[i + 1] + h16[i];
        u32 tot = suf[0];
        u32 above = tot;
#pragma unroll
        for (int off = 1; off < 32; off <<= 1) {
            u32 v = __shfl_down_sync(0xffffffffu, above, off);
            if (lane + off < 32) above += v;
        }
        above -= tot;                                     // counts in strictly higher bins
        u32 G = __shfl_sync(0xffffffffu, above + tot, 0); // total nonzero count

        u32 vth = 0u;   // fallback: fewer than K positives -> threshold 0, ties fill
        if (G >= KSEL) {
            int besti = -1;
#pragma unroll
            for (int i = 0; i < 16; ++i)
                if (suf[i] + above >= KSEL) besti = i;
            int bbin  = (besti >= 0) ? (lane * 16 + besti) : -1;
            int bstar = __reduce_max_sync(0xffffffffu, bbin);
            u32 myAbove = 0;
            if (bbin == bstar) myAbove = suf[besti] + above - h16[besti];
            u32 omask = __ballot_sync(0xffffffffu, bbin == bstar);
            int owner = __ffs(omask) - 1;
            u32 cntAbove = __shfl_sync(0xffffffffu, myAbove, owner);
            int m = KSEL - (int)cntAbove;                 // m-th largest inside bin bstar

            // boundary-bin candidate mask (in registers)
            u32 candm = 0;
#pragma unroll
            for (int s = 0; s < 16; ++s)
                if (zb[s] && (int)min(zb[s] >> SHIFT, (u32)(NBIN - 1)) == bstar)
                    candm |= (1u << s);
            int cc = __popc(candm);
            int c  = __reduce_add_sync(0xffffffffu, (u32)cc);

            if (c <= 32) {
                // compact candidates into 32-entry buffer via ballot-prefix
                int excl = cc;
#pragma unroll
                for (int off = 1; off < 32; off <<= 1) {
                    int v = __shfl_up_sync(0xffffffffu, excl, off);
                    if (lane >= off) excl += v;
                }
                excl -= cc;
                u32 mrem = candm; int pos = excl;
                while (mrem) {
                    int s = __ffs(mrem) - 1; mrem &= mrem - 1;
                    cand[pos++] = zb[s];
                }
                __syncwarp();
                u32 v = (lane < c) ? cand[lane] : 0u;
#pragma unroll
                for (int kk = 2; kk <= 32; kk <<= 1)
#pragma unroll
                    for (int j = kk >> 1; j > 0; j >>= 1) {
                        u32 o = __shfl_xor_sync(0xffffffffu, v, j);
                        bool keepMax = ((lane & j) == 0) == ((lane & kk) == 0);
                        u32 mx = v > o ? v : o, mn = v > o ? o : v;
                        v = keepMax ? mx : mn;
                    }
                vth = __shfl_sync(0xffffffffu, v, m - 1);
            } else {
                // rare: in-register bitwise binary search within bin bstar
                u32 t = ((u32)bstar) << SHIFT;
                for (int bit = SHIFT - 1; bit >= 0; --bit) {
                    u32 ttry = t | ((1u << bit) - 1u);
                    u32 cnt = 0;
#pragma unroll
                    for (int s = 0; s < 16; ++s)
                        cnt += (((candm >> s) & 1u) && (zb[s] > ttry)) ? 1u : 0u;
                    cnt = __reduce_add_sync(0xffffffffu, cnt);
                    if ((int)cnt >= m) t |= (1u << bit);
                }
                vth = t;
            }
        }

        // selection: all > vth, plus ties == vth in ascending index order (jax semantics)
        u32 gtm = 0, eqm = 0;
#pragma unroll
        for (int s = 0; s < 16; ++s) {
            if (zb[s] >  vth) gtm |= (1u << s);
            if (zb[s] == vth) eqm |= (1u << s);
        }
        int e = KSEL - (int)__reduce_add_sync(0xffffffffu, (u32)__popc(gtm));
        u32 selm = gtm;
        while (e > 0) {
            int sm2 = -1, jmin = 0x7fffffff;
            u32 t = eqm;
            while (t) {                      // lane's lowest-j tie
                int s = __ffs(t) - 1; t &= t - 1;
                int j = jmap(s);
                if (j < jmin) { jmin = j; sm2 = s; }
            }
            int jw = __reduce_min_sync(0xffffffffu, (u32)jmin);
            if (sm2 >= 0 && jmin == jw) { selm |= 1u << sm2; eqm &= ~(1u << sm2); }
            --e;
        }

        // compact selected (val, j) via ballot-prefix
        {
            int cnt  = __popc(selm);
            int excl = cnt;
#pragma unroll
            for (int off = 1; off < 32; off <<= 1) {
                int v = __shfl_up_sync(0xffffffffu, excl, off);
                if (lane >= off) excl += v;
            }
            excl -= cnt;
            u32 mrem = selm;
            int pos  = excl;
            while (mrem) {
                int s = __ffs(mrem) - 1; mrem &= mrem - 1;
                sel[pos++] = ((u64)zb[s] << 32) | (u32)jmap(s);
            }
        }

        // write z_sparse row (coalesced float4, streaming)
        float* zrow = out_z + row * (size_t)LAT;
#pragma unroll
        for (int q = 0; q < 4; ++q) {
            float4 o;
            o.x = ((selm >> (4 * q + 0)) & 1u) ? __uint_as_float(zb[4 * q + 0]) : 0.f;
            o.y = ((selm >> (4 * q + 1)) & 1u) ? __uint_as_float(zb[4 * q + 1]) : 0.f;
            o.z = ((selm >> (4 * q + 2)) & 1u) ? __uint_as_float(zb[4 * q + 2]) : 0.f;
            o.w = ((selm >> (4 * q + 3)) & 1u) ? __uint_as_float(zb[4 * q + 3]) : 0.f;
            int half = (q < 2) ? h : (1 - h);
            __stcs((float4*)(zrow + 256 * half + 128 * (q & 1) + 4 * lane), o);
        }
        __syncwarp();

        // sparse decode: lane owns outputs i = 2*lane, 2*lane+1 ; dual accumulators
        u64 a0 = dbias, a1 = pack2(0.f);
#pragma unroll 8
        for (int p = 0; p < KSEL; p += 2) {
            u64 sv0 = sel[p], sv1 = sel[p + 1];
            u64 vp0 = pack2(__uint_as_float((u32)(sv0 >> 32)));
            u64 vp1 = pack2(__uint_as_float((u32)(sv1 >> 32)));
            u64 w0  = *(const u64*)(g_decWT + (size_t)(u32)sv0 * IN_DIM + 2 * lane);
            u64 w1  = *(const u64*)(g_decWT + (size_t)(u32)sv1 * IN_DIM + 2 * lane);
            fma2(a0, vp0, w0);
            fma2(a1, vp1, w1);
        }
        __stcs((u64*)(out_x + row * (size_t)IN_DIM + 2 * lane), add2(a0, a1));
    }
}

extern "C" void kernel_launch(void* const* d_in, const int* in_sizes, int n_in,
                              void* d_out, int out_size) {
    const float* x    = (const float*)d_in[0];
    const float* encW = (const float*)d_in[1];
    const float* encb = (const float*)d_in[2];
    const float* decW = (const float*)d_in[3];
    const float* decb = (const float*)d_in[4];

    float* out = (float*)d_out;
    const long long B64  = (long long)BATCH * IN_DIM;
    const long long B512 = (long long)BATCH * LAT;

    float* ox = nullptr;
    float* oz = nullptr;
    if ((long long)out_size == B64 + B512) { ox = out; oz = out + B64; }
    else if ((long long)out_size == B512) { oz = out; }
    else if ((long long)out_size == B64)  { ox = out; }
    else { ox = out; oz = out + B64; }

    cudaFuncSetAttribute(sae_fused, cudaFuncAttributeMaxDynamicSharedMemorySize, SMEM_BYTES);

    prep_transpose<<<(LAT * IN_DIM + 255) / 256, 256>>>(encW, decW);
    sae_fused<<<BATCH / ROWS_PER_CTA, 256, SMEM_BYTES>>>(x, encb, decb, ox, oz);
}

// round 15
// speedup vs baseline: 1.0018x; 1.0018x over previous
#include <cuda_runtime.h>
#include <cstdint>

#define BATCH        262144
#define IN_DIM       64
#define LAT          512
#define KSEL         32
#define NWARPS       8          // 256 threads
#define ROWS_PER_CTA 32
#define NBIN         512
#define SHIFT        21
#define CHUNK_K      16
#define NCHUNK       (IN_DIM / CHUNK_K)

typedef unsigned int       u32;
typedef unsigned long long u64;

// Transposed weights (prep kernel fills these each launch; tiny cost).
__device__ __align__(16) float g_encWT[IN_DIM * LAT];   // [k][j]
__device__ __align__(16) float g_decWT[LAT * IN_DIM];   // [j][i]
// Fallback sink if the harness only scores one of the two outputs.
__device__ float g_scratch[(size_t)BATCH * LAT];

// ---------------- packed f32x2 helpers ----------------
__device__ __forceinline__ u64 pack2(float x) {
    u64 r;
    asm("mov.b64 %0, {%1, %1};" : "=l"(r) : "r"(__float_as_uint(x)));
    return r;
}
__device__ __forceinline__ void fma2(u64& d, u64 a, u64 b) {
    asm("fma.rn.f32x2 %0, %1, %2, %0;" : "+l"(d) : "l"(a), "l"(b));
}
__device__ __forceinline__ u64 add2(u64 a, u64 b) {
    u64 r;
    asm("add.rn.f32x2 %0, %1, %2;" : "=l"(r) : "l"(a), "l"(b));
    return r;
}
__device__ __forceinline__ float2 unpack2(u64 v) {
    float2 f;
    asm("mov.b64 {%0, %1}, %2;" : "=f"(f.x), "=f"(f.y) : "l"(v));
    return f;
}

// ---------------- prep: transpose both weight matrices ----------------
__global__ void prep_transpose(const float* __restrict__ encW,   // [LAT][IN_DIM]
                               const float* __restrict__ decW) { // [IN_DIM][LAT]
    int idx = blockIdx.x * blockDim.x + threadIdx.x;
    if (idx < LAT * IN_DIM) {
        int j = idx / IN_DIM, k = idx - j * IN_DIM;
        g_encWT[k * LAT + j] = encW[idx];
        int i2 = idx / LAT, j2 = idx - i2 * LAT;
        g_decWT[j2 * IN_DIM + i2] = decW[idx];
    }
}

// ---------------- dynamic smem layout (u32 words) ----------------
// region A (32 KB): weight chunks during encoder, half-exchange buffer afterwards
#define OFF_A      0                                   // 8192 u32
#define OFF_X      8192                                // 32*64 floats  = 8 KB
#define OFF_HIST   (OFF_X + ROWS_PER_CTA * IN_DIM)     // 8 warps * 256 u32 (packed u16x2) = 8 KB
#define OFF_CAND   (OFF_HIST + NWARPS * (NBIN / 2))    // 8 warps * 32 u32 = 1 KB
#define OFF_SEL    (OFF_CAND + NWARPS * 32)            // 8 warps * 32 u64 = 2 KB
#define OFF_CNT    (OFF_SEL + NWARPS * KSEL * 2)       // 8
#define SMEM_WORDS (OFF_CNT + NWARPS)
#define SMEM_BYTES (SMEM_WORDS * 4)

// ---------------- fused encoder + exact top-k + sparse decoder ----------------
__global__ __launch_bounds__(256, 2)
void sae_fused(const float* __restrict__ x,
               const float* __restrict__ enc_b,
               const float* __restrict__ dec_b,
               float* out_x_in,      // [B][64]  (may be null)
               float* out_z_in)      // [B][512] (may be null)
{
    extern __shared__ u32 sm[];
    float* s_w   = (float*)(sm + OFF_A);      // encoder phase
    u32*   s_ex  = sm + OFF_A;                // exchange phase (same region)
    float* s_x   = (float*)(sm + OFF_X);
    u32*   s_hist= sm + OFF_HIST;
    u32*   s_cand= sm + OFF_CAND;
    u64*   s_sel = (u64*)(sm + OFF_SEL);
    u32*   s_cnt = sm + OFF_CNT;

    float* out_x = out_x_in ? out_x_in : g_scratch;
    float* out_z = out_z_in ? out_z_in : g_scratch;

    const int tid  = threadIdx.x;
    const int warp = tid >> 5;
    const int lane = tid & 31;
    const int h    = warp & 1;          // latent half
    const int g    = warp >> 1;         // row group (8 rows)
    const size_t rowBase = (size_t)blockIdx.x * ROWS_PER_CTA;

    // ---- stage x tile (32 rows x 64 = 512 float4), streaming loads ----
    {
        const float4* xs = (const float4*)(x + rowBase * IN_DIM);
        float4* xd = (float4*)s_x;
        xd[tid]       = __ldcs(xs + tid);
        xd[tid + 256] = __ldcs(xs + tid + 256);
    }

    // ---- encoder: warp owns 8 rows (8g..8g+7) x 256 latents (half h).
    // lane owns latents l = 128t + 4*lane + (2p+e), acc[r][2t+p] = f32x2 latent pair.
    u64 acc[8][4];
    {
        const float4 b4a = *(const float4*)(enc_b + 256 * h + 4 * lane);
        const float4 b4b = *(const float4*)(enc_b + 256 * h + 128 + 4 * lane);
        u64 b0 = pack2(b4a.x) , b1 = pack2(b4a.z);
        u64 b2 = pack2(b4b.x) , b3 = pack2(b4b.z);
        // NOTE: pairs are (l, l+1): acc[r][2t+p] covers latents 128t+4lane+2p, +1
        u64 p00 = pack2(b4a.x), p01 = pack2(b4a.z), p10 = pack2(b4b.x), p11 = pack2(b4b.z);
        // but each f32x2 lane half must hold the bias of ITS latent:
        // latent pair (j, j+1) -> (bias[j], bias[j+1])
        u64 q00, q01, q10, q11;
        asm("mov.b64 %0, {%1, %2};" : "=l"(q00) : "r"(__float_as_uint(b4a.x)), "r"(__float_as_uint(b4a.y)));
        asm("mov.b64 %0, {%1, %2};" : "=l"(q01) : "r"(__float_as_uint(b4a.z)), "r"(__float_as_uint(b4a.w)));
        asm("mov.b64 %0, {%1, %2};" : "=l"(q10) : "r"(__float_as_uint(b4b.x)), "r"(__float_as_uint(b4b.y)));
        asm("mov.b64 %0, {%1, %2};" : "=l"(q11) : "r"(__float_as_uint(b4b.z)), "r"(__float_as_uint(b4b.w)));
        (void)b0;(void)b1;(void)b2;(void)b3;(void)p00;(void)p01;(void)p10;(void)p11;
#pragma unroll
        for (int r = 0; r < 8; ++r) {
            acc[r][0] = q00; acc[r][1] = q01; acc[r][2] = q10; acc[r][3] = q11;
        }
    }

    const float* xw = s_x + (8 * g) * IN_DIM;

    for (int c = 0; c < NCHUNK; ++c) {
        __syncthreads();   // previous chunk fully consumed (and x staged, first iter)
        {
            const float4* wsrc = (const float4*)(g_encWT + c * CHUNK_K * LAT);
            float4* wdst = (float4*)s_w;
#pragma unroll
            for (int i = 0; i < 8; ++i) wdst[tid + i * 256] = __ldcg(wsrc + tid + i * 256);
        }
        __syncthreads();

#pragma unroll
        for (int kq = 0; kq < CHUNK_K / 4; ++kq) {
            float4 xq[8];
#pragma unroll
            for (int r = 0; r < 8; ++r)
                xq[r] = *(const float4*)(xw + r * IN_DIM + c * CHUNK_K + kq * 4);

#pragma unroll
            for (int kk = 0; kk < 4; ++kk) {
                const int ksm = kq * 4 + kk;
                u64 xp[8];
#pragma unroll
                for (int r = 0; r < 8; ++r)
                    xp[r] = pack2(((const float*)&xq[r])[kk]);
                ulonglong2 w0 = *(const ulonglong2*)(s_w + ksm * LAT + 256 * h +       4 * lane);
                ulonglong2 w1 = *(const ulonglong2*)(s_w + ksm * LAT + 256 * h + 128 + 4 * lane);
#pragma unroll
                for (int r = 0; r < 8; ++r) {
                    fma2(acc[r][0], xp[r], w0.x);
                    fma2(acc[r][1], xp[r], w0.y);
                    fma2(acc[r][2], xp[r], w1.x);
                    fma2(acc[r][3], xp[r], w1.y);
                }
            }
        }
    }
    __syncthreads();   // all warps done with s_w -> safe to overlay exchange buffer

    // ---- half-exchange: warp w gives partner (w^1) its half of partner's topk rows.
    // topk rows of warp w = 8g + 4h .. +3  (acc indices 4h..4h+3)
    // so warp w WRITES acc rows 4*(1-h)..+3 into buffer slot of partner.
    {
        const int pw = warp ^ 1;
#pragma unroll
        for (int rr = 0; rr < 4; ++rr) {
            const int r = 4 * (1 - h) + rr;
            float2 f0 = unpack2(acc[r][0]), f1 = unpack2(acc[r][1]);
            float2 f2 = unpack2(acc[r][2]), f3 = unpack2(acc[r][3]);
            uint4 a, b;
            a.x = (f0.x > 0.f) ? __float_as_uint(f0.x) : 0u;
            a.y = (f0.y > 0.f) ? __float_as_uint(f0.y) : 0u;
            a.z = (f1.x > 0.f) ? __float_as_uint(f1.x) : 0u;
            a.w = (f1.y > 0.f) ? __float_as_uint(f1.y) : 0u;
            b.x = (f2.x > 0.f) ? __float_as_uint(f2.x) : 0u;
            b.y = (f2.y > 0.f) ? __float_as_uint(f2.y) : 0u;
            b.z = (f3.x > 0.f) ? __float_as_uint(f3.x) : 0u;
            b.w = (f3.y > 0.f) ? __float_as_uint(f3.y) : 0u;
            *(uint4*)(s_ex + pw * 1024 + rr * 256 +       4 * lane) = a;
            *(uint4*)(s_ex + pw * 1024 + rr * 256 + 128 + 4 * lane) = b;
        }
    }
    __syncthreads();

    const u64 dbias = *(const u64*)(dec_b + 2 * lane);
    u32* hist = s_hist + warp * (NBIN / 2);
    u32* cand = s_cand + warp * 32;
    u64* sel  = s_sel  + warp * KSEL;

    // slot -> latent index (s<8: own half from acc; s>=8: partner half from smem)
    auto jmap = [&](int s) -> int {
        int half = (s < 8) ? h : (1 - h);
        return 256 * half + 128 * ((s >> 2) & 1) + 4 * lane + (s & 3);
    };

    // ---- per-row: relu -> exact top-32 (radix select on float bits) -> writes ----
    for (int rr = 0; rr < 4; ++rr) {
        const int    r   = 4 * h + rr;               // acc index of this topk row
        const size_t row = rowBase + 8 * g + 4 * h + rr;

        u32 zb[16];
#pragma unroll
        for (int i = 0; i < 4; ++i) {
            float2 f = unpack2(acc[r][i]);
            zb[2 * i]     = (f.x > 0.f) ? __float_as_uint(f.x) : 0u;
            zb[2 * i + 1] = (f.y > 0.f) ? __float_as_uint(f.y) : 0u;
        }
        {
            uint4 a = *(const uint4*)(s_ex + warp * 1024 + rr * 256 +       4 * lane);
            uint4 b = *(const uint4*)(s_ex + warp * 1024 + rr * 256 + 128 + 4 * lane);
            zb[8] = a.x; zb[9] = a.y; zb[10] = a.z; zb[11] = a.w;
            zb[12] = b.x; zb[13] = b.y; zb[14] = b.z; zb[15] = b.w;
        }

        // 512-bin histogram on bits[30:21], packed 2 bins/u32 (u16 counts); skip zeros
        {
            uint4 z4 = make_uint4(0u, 0u, 0u, 0u);
            ((uint4*)hist)[lane * 2]     = z4;
            ((uint4*)hist)[lane * 2 + 1] = z4;
        }
        __syncwarp();
#pragma unroll
        for (int s = 0; s < 16; ++s)
            if (zb[s]) {
                u32 b = min(zb[s] >> SHIFT, (u32)(NBIN - 1));
                atomicAdd(&hist[b >> 1], 1u << ((b & 1) * 16));
            }
        __syncwarp();

        // lane owns bins [16*lane, 16*lane+16) = words [8*lane, 8*lane+8)
        u32 h16[16];
        {
            uint4 wa = ((const uint4*)hist)[lane * 2];
            uint4 wb = ((const uint4*)hist)[lane * 2 + 1];
            u32 wsv[8] = {wa.x, wa.y, wa.z, wa.w, wb.x, wb.y, wb.z, wb.w};
#pragma unroll
            for (int i = 0; i < 8; ++i) {
                h16[2 * i]     = wsv[i] & 0xffffu;
                h16[2 * i + 1] = wsv[i] >> 16;
            }
        }
        u32 suf[16];
        suf[15] = h16[15];
#pragma unroll
        for (int i = 14; i >= 0; --i) suf[i] = suf[i + 1] + h16[i];
        u32 tot = suf[0];
        u32 above = tot;
#pragma unroll
        for (int off = 1; off < 32; off <<= 1) {
            u32 v = __shfl_down_sync(0xffffffffu, above, off);
            if (lane + off < 32) above += v;
        }
        above -= tot;                                     // counts in strictly higher bins
        u32 G = __shfl_sync(0xffffffffu, above + tot, 0); // total nonzero count

        u32 vth = 0u;   // fallback: fewer than K positives -> threshold 0, ties fill
        if (G >= KSEL) {
            int besti = -1;
#pragma unroll
            for (int i = 0; i < 16; ++i)
                if (suf[i] + above >= KSEL) besti = i;
            int bbin  = (besti >= 0) ? (lane * 16 + besti) : -1;
            int bstar = __reduce_max_sync(0xffffffffu, bbin);
            u32 myAbove = 0;
            if (bbin == bstar) myAbove = suf[besti] + above - h16[besti];
            u32 omask = __ballot_sync(0xffffffffu, bbin == bstar);
            int owner = __ffs(omask) - 1;
            u32 cntAbove = __shfl_sync(0xffffffffu, myAbove, owner);
            int m = KSEL - (int)cntAbove;                 // m-th largest inside bin bstar

            // boundary-bin candidate mask (in registers)
            u32 candm = 0;
#pragma unroll
            for (int s = 0; s < 16; ++s)
                if (zb[s] && (int)min(zb[s] >> SHIFT, (u32)(NBIN - 1)) == bstar)
                    candm |= (1u << s);
            int cc = __popc(candm);
            int c  = __reduce_add_sync(0xffffffffu, (u32)cc);

            if (c <= 32) {
                // compact candidates into 32-entry buffer via ballot-prefix
                int excl = cc;
#pragma unroll
                for (int off = 1; off < 32; off <<= 1) {
                    int v = __shfl_up_sync(0xffffffffu, excl, off);
                    if (lane >= off) excl += v;
                }
                excl -= cc;
                u32 mrem = candm; int pos = excl;
                while (mrem) {
                    int s = __ffs(mrem) - 1; mrem &= mrem - 1;
                    cand[pos++] = zb[s];
                }
                __syncwarp();
                u32 v = (lane < c) ? cand[lane] : 0u;
#pragma unroll
                for (int kk = 2; kk <= 32; kk <<= 1)
#pragma unroll
                    for (int j = kk >> 1; j > 0; j >>= 1) {
                        u32 o = __shfl_xor_sync(0xffffffffu, v, j);
                        bool keepMax = ((lane & j) == 0) == ((lane & kk) == 0);
                        u32 mx = v > o ? v : o, mn = v > o ? o : v;
                        v = keepMax ? mx : mn;
                    }
                vth = __shfl_sync(0xffffffffu, v, m - 1);
            } else {
                // rare: in-register bitwise binary search within bin bstar
                u32 t = ((u32)bstar) << SHIFT;
                for (int bit = SHIFT - 1; bit >= 0; --bit) {
                    u32 ttry = t | ((1u << bit) - 1u);
                    u32 cnt = 0;
#pragma unroll
                    for (int s = 0; s < 16; ++s)
                        cnt += (((candm >> s) & 1u) && (zb[s] > ttry)) ? 1u : 0u;
                    cnt = __reduce_add_sync(0xffffffffu, cnt);
                    if ((int)cnt >= m) t |= (1u << bit);
                }
                vth = t;
            }
        }

        // selection: all > vth, plus ties == vth in ascending index order (jax semantics)
        u32 gtm = 0, eqm = 0;
#pragma unroll
        for (int s = 0; s < 16; ++s) {
            if (zb[s] >  vth) gtm |= (1u << s);
            if (zb[s] == vth) eqm |= (1u << s);
        }
        int e = KSEL - (int)__reduce_add_sync(0xffffffffu, (u32)__popc(gtm));
        u32 selm = gtm;
        while (e > 0) {
            int sm2 = -1, jmin = 0x7fffffff;
            u32 t = eqm;
            while (t) {                      // lane's lowest-j tie
                int s = __ffs(t) - 1; t &= t - 1;
                int j = jmap(s);
                if (j < jmin) { jmin = j; sm2 = s; }
            }
            int jw = __reduce_min_sync(0xffffffffu, (u32)jmin);
            if (sm2 >= 0 && jmin == jw) { selm |= 1u << sm2; eqm &= ~(1u << sm2); }
            --e;
        }

        // compact selected (val, j) via ballot-prefix
        {
            int cnt  = __popc(selm);
            int excl = cnt;
#pragma unroll
            for (int off = 1; off < 32; off <<= 1) {
                int v = __shfl_up_sync(0xffffffffu, excl, off);
                if (lane >= off) excl += v;
            }
            excl -= cnt;
            u32 mrem = selm;
            int pos  = excl;
            while (mrem) {
                int s = __ffs(mrem) - 1; mrem &= mrem - 1;
                sel[pos++] = ((u64)zb[s] << 32) | (u32)jmap(s);
            }
        }

        // write z_sparse row (coalesced float4, streaming)
        float* zrow = out_z + row * (size_t)LAT;
#pragma unroll
        for (int q = 0; q < 4; ++q) {
            float4 o;
            o.x = ((selm >> (4 * q + 0)) & 1u) ? __uint_as_float(zb[4 * q + 0]) : 0.f;
            o.y = ((selm >> (4 * q + 1)) & 1u) ? __uint_as_float(zb[4 * q + 1]) : 0.f;
            o.z = ((selm >> (4 * q + 2)) & 1u) ? __uint_as_float(zb[4 * q + 2]) : 0.f;
            o.w = ((selm >> (4 * q + 3)) & 1u) ? __uint_as_float(zb[4 * q + 3]) : 0.f;
            int half = (q < 2) ? h : (1 - h);
            __stcs((float4*)(zrow + 256 * half + 128 * (q & 1) + 4 * lane), o);
        }
        __syncwarp();

        // sparse decode: lane owns outputs i = 2*lane, 2*lane+1 ; dual accumulators
        u64 a0 = dbias, a1 = pack2(0.f);
#pragma unroll 8
        for (int p = 0; p < KSEL; p += 2) {
            u64 sv0 = sel[p], sv1 = sel[p + 1];
            u64 vp0 = pack2(__uint_as_float((u32)(sv0 >> 32)));
            u64 vp1 = pack2(__uint_as_float((u32)(sv1 >> 32)));
            u64 w0  = *(const u64*)(g_decWT + (size_t)(u32)sv0 * IN_DIM + 2 * lane);
            u64 w1  = *(const u64*)(g_decWT + (size_t)(u32)sv1 * IN_DIM + 2 * lane);
            fma2(a0, vp0, w0);
            fma2(a1, vp1, w1);
        }
        __stcs((u64*)(out_x + row * (size_t)IN_DIM + 2 * lane), add2(a0, a1));
    }
}

extern "C" void kernel_launch(void* const* d_in, const int* in_sizes, int n_in,
                              void* d_out, int out_size) {
    const float* x    = (const float*)d_in[0];
    const float* encW = (const float*)d_in[1];
    const float* encb = (const float*)d_in[2];
    const float* decW = (const float*)d_in[3];
    const float* decb = (const float*)d_in[4];

    float* out = (float*)d_out;
    const long long B64  = (long long)BATCH * IN_DIM;
    const long long B512 = (long long)BATCH * LAT;

    float* ox = nullptr;
    float* oz = nullptr;
    if ((long long)out_size == B64 + B512) { ox = out; oz = out + B64; }
    else if ((long long)out_size == B512) { oz = out; }
    else if ((long long)out_size == B64)  { ox = out; }
    else { ox = out; oz = out + B64; }

    cudaFuncSetAttribute(sae_fused, cudaFuncAttributeMaxDynamicSharedMemorySize, SMEM_BYTES);

    prep_transpose<<<(LAT * IN_DIM + 255) / 256, 256>>>(encW, decW);
    sae_fused<<<BATCH / ROWS_PER_CTA, 256, SMEM_BYTES>>>(x, encb, decb, ox, oz);
}

// round 16
// speedup vs baseline: 1.3938x; 1.3913x over previous
#include <cuda_runtime.h>
#include <cstdint>

#define BATCH        262144
#define IN_DIM       64
#define LAT          512
#define KSEL         32
#define NBIN         512
#define SHIFT        21
#define CHUNK_K      16
#define NCHUNK       (IN_DIM / CHUNK_K)

typedef unsigned int       u32;
typedef unsigned long long u64;

// Transposed weights (prep kernel fills these each launch; tiny cost).
__device__ __align__(16) float g_encWT[IN_DIM * LAT];   // [k][j]
__device__ __align__(16) float g_decWT[LAT * IN_DIM];   // [j][i]
// Staging / fallback sink.
__device__ float g_scratch[(size_t)BATCH * LAT];

// ---------------- packed f32x2 helpers ----------------
__device__ __forceinline__ u64 pack2(float x) {
    u64 r;
    asm("mov.b64 %0, {%1, %1};" : "=l"(r) : "r"(__float_as_uint(x)));
    return r;
}
__device__ __forceinline__ u64 packpair(float lo, float hi) {
    u64 r;
    asm("mov.b64 %0, {%1, %2};" : "=l"(r) : "r"(__float_as_uint(lo)), "r"(__float_as_uint(hi)));
    return r;
}
__device__ __forceinline__ void fma2(u64& d, u64 a, u64 b) {
    asm("fma.rn.f32x2 %0, %1, %2, %0;" : "+l"(d) : "l"(a), "l"(b));
}
__device__ __forceinline__ u64 add2(u64 a, u64 b) {
    u64 r;
    asm("add.rn.f32x2 %0, %1, %2;" : "=l"(r) : "l"(a), "l"(b));
    return r;
}
__device__ __forceinline__ float2 unpack2(u64 v) {
    float2 f;
    asm("mov.b64 {%0, %1}, %2;" : "=f"(f.x), "=f"(f.y) : "l"(v));
    return f;
}

// ---------------- prep: transpose both weight matrices ----------------
__global__ void prep_transpose(const float* __restrict__ encW,   // [LAT][IN_DIM]
                               const float* __restrict__ decW) { // [IN_DIM][LAT]
    int idx = blockIdx.x * blockDim.x + threadIdx.x;
    if (idx < LAT * IN_DIM) {
        int j = idx / IN_DIM, k = idx - j * IN_DIM;
        g_encWT[k * LAT + j] = encW[idx];
        int i2 = idx / LAT, j2 = idx - i2 * LAT;
        g_decWT[j2 * IN_DIM + i2] = decW[idx];
    }
}

// ================= kernel 1: encoder GEMM + relu, writes z bits =================
#define K1_SMEM_WORDS (CHUNK_K * LAT + 32 * IN_DIM)   // weight chunk + x tile
#define K1_SMEM_BYTES (K1_SMEM_WORDS * 4)

__global__ __launch_bounds__(256, 2)
void sae_enc(const float* __restrict__ x,
             const float* __restrict__ enc_b,
             float* __restrict__ zout)       // [B][512], relu'd bits
{
    extern __shared__ u32 sm[];
    float* s_w = (float*)sm;                        // 32 KB weight chunk
    float* s_x = (float*)(sm + CHUNK_K * LAT);      // 8 KB x tile

    const int tid  = threadIdx.x;
    const int warp = tid >> 5;
    const int lane = tid & 31;
    const int h    = warp & 1;
    const int g    = warp >> 1;
    const size_t rowBase = (size_t)blockIdx.x * 32;

    {
        const float4* xs = (const float4*)(x + rowBase * IN_DIM);
        float4* xd = (float4*)s_x;
        xd[tid]       = __ldcs(xs + tid);
        xd[tid + 256] = __ldcs(xs + tid + 256);
    }

    u64 acc[8][4];
    {
        const float4 b4a = *(const float4*)(enc_b + 256 * h + 4 * lane);
        const float4 b4b = *(const float4*)(enc_b + 256 * h + 128 + 4 * lane);
        u64 q00 = packpair(b4a.x, b4a.y), q01 = packpair(b4a.z, b4a.w);
        u64 q10 = packpair(b4b.x, b4b.y), q11 = packpair(b4b.z, b4b.w);
#pragma unroll
        for (int r = 0; r < 8; ++r) {
            acc[r][0] = q00; acc[r][1] = q01; acc[r][2] = q10; acc[r][3] = q11;
        }
    }

    const float* xw = s_x + (8 * g) * IN_DIM;

    for (int c = 0; c < NCHUNK; ++c) {
        __syncthreads();   // previous chunk consumed (and x staged, first iter)
        {
            const float4* wsrc = (const float4*)(g_encWT + c * CHUNK_K * LAT);
            float4* wdst = (float4*)s_w;
#pragma unroll
            for (int i = 0; i < 8; ++i) wdst[tid + i * 256] = __ldcg(wsrc + tid + i * 256);
        }
        __syncthreads();

#pragma unroll
        for (int kq = 0; kq < CHUNK_K / 4; ++kq) {
            float4 xq[8];
#pragma unroll
            for (int r = 0; r < 8; ++r)
                xq[r] = *(const float4*)(xw + r * IN_DIM + c * CHUNK_K + kq * 4);

#pragma unroll
            for (int kk = 0; kk < 4; ++kk) {
                const int ksm = kq * 4 + kk;
                u64 xp[8];
#pragma unroll
                for (int r = 0; r < 8; ++r)
                    xp[r] = pack2(((const float*)&xq[r])[kk]);
                ulonglong2 w0 = *(const ulonglong2*)(s_w + ksm * LAT + 256 * h +       4 * lane);
                ulonglong2 w1 = *(const ulonglong2*)(s_w + ksm * LAT + 256 * h + 128 + 4 * lane);
#pragma unroll
                for (int r = 0; r < 8; ++r) {
                    fma2(acc[r][0], xp[r], w0.x);
                    fma2(acc[r][1], xp[r], w0.y);
                    fma2(acc[r][2], xp[r], w1.x);
                    fma2(acc[r][3], xp[r], w1.y);
                }
            }
        }
    }

    u32* zo = (u32*)zout;
#pragma unroll
    for (int r = 0; r < 8; ++r) {
        const size_t row = rowBase + 8 * g + r;
        float2 f0 = unpack2(acc[r][0]), f1 = unpack2(acc[r][1]);
        float2 f2 = unpack2(acc[r][2]), f3 = unpack2(acc[r][3]);
        uint4 a, b;
        a.x = (f0.x > 0.f) ? __float_as_uint(f0.x) : 0u;
        a.y = (f0.y > 0.f) ? __float_as_uint(f0.y) : 0u;
        a.z = (f1.x > 0.f) ? __float_as_uint(f1.x) : 0u;
        a.w = (f1.y > 0.f) ? __float_as_uint(f1.y) : 0u;
        b.x = (f2.x > 0.f) ? __float_as_uint(f2.x) : 0u;
        b.y = (f2.y > 0.f) ? __float_as_uint(f2.y) : 0u;
        b.z = (f3.x > 0.f) ? __float_as_uint(f3.x) : 0u;
        b.w = (f3.y > 0.f) ? __float_as_uint(f3.y) : 0u;
        __stcs((uint4*)(zo + row * LAT + 256 * h +       4 * lane), a);
        __stcs((uint4*)(zo + row * LAT + 256 * h + 128 + 4 * lane), b);
    }
}

// ================= kernel 2: exact top-32 + scatter + sparse decode =================
// slot s (0..15) of lane -> latent j = 128*(s>>2) + 4*lane + (s&3)
__global__ __launch_bounds__(128, 8)
void sae_topk(const float* __restrict__ zin,     // [B][512] relu'd bits
              const float* __restrict__ dec_b,
              float* __restrict__ out_x,         // [B][64]
              float* __restrict__ out_z)         // [B][512] (may alias zin)
{
    __shared__ u32 s_hist[4][NBIN / 2];   // packed u16x2 counts
    __shared__ u32 s_cand[4][32];
    __shared__ u64 s_sel [4][KSEL];

    const int tid  = threadIdx.x;
    const int warp = tid >> 5;
    const int lane = tid & 31;
    u32* hist = s_hist[warp];
    u32* cand = s_cand[warp];
    u64* sel  = s_sel[warp];
    const u64 dbias = *(const u64*)(dec_b + 2 * lane);

    for (int rr = 0; rr < 4; ++rr) {
        const size_t row = (size_t)blockIdx.x * 16 + warp * 4 + rr;
        const u32* zrow = (const u32*)(zin + row * (size_t)LAT);

        u32 zb[16];
#pragma unroll
        for (int t = 0; t < 4; ++t) {
            uint4 v = __ldcs((const uint4*)(zrow + t * 128 + 4 * lane));
            zb[4 * t] = v.x; zb[4 * t + 1] = v.y; zb[4 * t + 2] = v.z; zb[4 * t + 3] = v.w;
        }

        // 512-bin histogram on bits[30:21] (clamped), packed 2 bins/u32; skip zeros
        {
            uint4 z4 = make_uint4(0u, 0u, 0u, 0u);
            ((uint4*)hist)[lane * 2]     = z4;
            ((uint4*)hist)[lane * 2 + 1] = z4;
        }
        __syncwarp();
#pragma unroll
        for (int s = 0; s < 16; ++s)
            if (zb[s]) {
                u32 b = min(zb[s] >> SHIFT, (u32)(NBIN - 1));
                atomicAdd(&hist[b >> 1], 1u << ((b & 1) * 16));
            }
        __syncwarp();

        u32 wsv[8];
        {
            uint4 wa = ((const uint4*)hist)[lane * 2];
            uint4 wb = ((const uint4*)hist)[lane * 2 + 1];
            wsv[0] = wa.x; wsv[1] = wa.y; wsv[2] = wa.z; wsv[3] = wa.w;
            wsv[4] = wb.x; wsv[5] = wb.y; wsv[6] = wb.z; wsv[7] = wb.w;
        }
        u32 tot = 0;
#pragma unroll
        for (int i = 0; i < 8; ++i) tot += (wsv[i] & 0xffffu) + (wsv[i] >> 16);

        u32 above = tot;
#pragma unroll
        for (int off = 1; off < 32; off <<= 1) {
            u32 v = __shfl_down_sync(0xffffffffu, above, off);
            if (lane + off < 32) above += v;
        }
        above -= tot;                                     // counts in strictly higher bins
        u32 G = __shfl_sync(0xffffffffu, above + tot, 0); // total nonzero count

        u32 vth = 0u;   // fallback: fewer than K positives -> threshold 0, ties fill
        if (G >= KSEL) {
            int besti = -1; u32 runbest = 0, hbest = 0, run = 0;
#pragma unroll
            for (int i = 15; i >= 0; --i) {
                u32 hh = (wsv[i >> 1] >> (16 * (i & 1))) & 0xffffu;
                run += hh;
                if (besti < 0 && run + above >= KSEL) { besti = i; hbest = hh; runbest = run; }
            }
            int bbin  = (besti >= 0) ? (lane * 16 + besti) : -1;
            int bstar = __reduce_max_sync(0xffffffffu, bbin);
            u32 myAbove = (bbin == bstar) ? (runbest - hbest + above) : 0u;
            u32 omask = __ballot_sync(0xffffffffu, bbin == bstar);
            int owner = __ffs(omask) - 1;
            u32 cntAbove = __shfl_sync(0xffffffffu, myAbove, owner);
            int m = KSEL - (int)cntAbove;                 // m-th largest inside bin bstar

            u32 candm = 0;
#pragma unroll
            for (int s = 0; s < 16; ++s)
                if (zb[s] && (int)min(zb[s] >> SHIFT, (u32)(NBIN - 1)) == bstar)
                    candm |= (1u << s);
            int cc = __popc(candm);
            int c  = __reduce_add_sync(0xffffffffu, (u32)cc);

            if (c <= 32) {
                int excl = cc;
#pragma unroll
                for (int off = 1; off < 32; off <<= 1) {
                    int v = __shfl_up_sync(0xffffffffu, excl, off);
                    if (lane >= off) excl += v;
                }
                excl -= cc;
                u32 mrem = candm; int pos = excl;
                while (mrem) {
                    int s = __ffs(mrem) - 1; mrem &= mrem - 1;
                    cand[pos++] = zb[s];
                }
                __syncwarp();
                u32 v = (lane < c) ? cand[lane] : 0u;
#pragma unroll
                for (int kk = 2; kk <= 32; kk <<= 1)
#pragma unroll
                    for (int j = kk >> 1; j > 0; j >>= 1) {
                        u32 o = __shfl_xor_sync(0xffffffffu, v, j);
                        bool keepMax = ((lane & j) == 0) == ((lane & kk) == 0);
                        u32 mx = v > o ? v : o, mn = v > o ? o : v;
                        v = keepMax ? mx : mn;
                    }
                vth = __shfl_sync(0xffffffffu, v, m - 1);
            } else {
                u32 t = 0u;
                for (int bit = 30; bit >= 0; --bit) {
                    u32 ttry = t | ((1u << bit) - 1u);
                    u32 cnt = 0;
#pragma unroll
                    for (int s = 0; s < 16; ++s)
                        cnt += (((candm >> s) & 1u) && (zb[s] > ttry)) ? 1u : 0u;
                    cnt = __reduce_add_sync(0xffffffffu, cnt);
                    if ((int)cnt >= m) t |= (1u << bit);
                }
                vth = t;
            }
        }

        // selection: all > vth, plus ties == vth in ascending index order (jax semantics)
        u32 gtm = 0, eqm = 0;
#pragma unroll
        for (int s = 0; s < 16; ++s) {
            if (zb[s] >  vth) gtm |= (1u << s);
            if (zb[s] == vth) eqm |= (1u << s);
        }
        int e = KSEL - (int)__reduce_add_sync(0xffffffffu, (u32)__popc(gtm));
        u32 selm = gtm;
        while (e > 0) {
            int  sm2  = __ffs(eqm) - 1;
            int  jmin = eqm ? (128 * (sm2 >> 2) + 4 * lane + (sm2 & 3)) : 0x7fffffff;
            int  jw   = __reduce_min_sync(0xffffffffu, (u32)jmin);
            if (eqm && jmin == jw) { selm |= 1u << sm2; eqm &= ~(1u << sm2); }
            --e;
        }

        // compact selected (val, j) via ballot-prefix
        {
            int cnt  = __popc(selm);
            int excl = cnt;
#pragma unroll
            for (int off = 1; off < 32; off <<= 1) {
                int v = __shfl_up_sync(0xffffffffu, excl, off);
                if (lane >= off) excl += v;
            }
            excl -= cnt;
            u32 mrem = selm;
            int pos  = excl;
            while (mrem) {
                int s = __ffs(mrem) - 1; mrem &= mrem - 1;
                int j = 128 * (s >> 2) + 4 * lane + (s & 3);
                sel[pos++] = ((u64)zb[s] << 32) | (u32)j;
            }
        }

        // write z_sparse row (full row, coalesced float4, streaming)
        float* zw = out_z + row * (size_t)LAT;
#pragma unroll
        for (int t = 0; t < 4; ++t) {
            float4 o;
            o.x = ((selm >> (4 * t + 0)) & 1u) ? __uint_as_float(zb[4 * t + 0]) : 0.f;
            o.y = ((selm >> (4 * t + 1)) & 1u) ? __uint_as_float(zb[4 * t + 1]) : 0.f;
            o.z = ((selm >> (4 * t + 2)) & 1u) ? __uint_as_float(zb[4 * t + 2]) : 0.f;
            o.w = ((selm >> (4 * t + 3)) & 1u) ? __uint_as_float(zb[4 * t + 3]) : 0.f;
            __stcs((float4*)(zw + t * 128 + 4 * lane), o);
        }
        __syncwarp();

        // sparse decode: lane owns outputs i = 2*lane, 2*lane+1 ; dual accumulators
        u64 a0 = dbias, a1 = pack2(0.f);
#pragma unroll 8
        for (int p = 0; p < KSEL; p += 2) {
            u64 sv0 = sel[p], sv1 = sel[p + 1];
            u64 vp0 = pack2(__uint_as_float((u32)(sv0 >> 32)));
            u64 vp1 = pack2(__uint_as_float((u32)(sv1 >> 32)));
            u64 w0  = *(const u64*)(g_decWT + (size_t)(u32)sv0 * IN_DIM + 2 * lane);
            u64 w1  = *(const u64*)(g_decWT + (size_t)(u32)sv1 * IN_DIM + 2 * lane);
            fma2(a0, vp0, w0);
            fma2(a1, vp1, w1);
        }
        __stcs((u64*)(out_x + row * (size_t)IN_DIM + 2 * lane), add2(a0, a1));
    }
}

extern "C" void kernel_launch(void* const* d_in, const int* in_sizes, int n_in,
                              void* d_out, int out_size) {
    const float* x    = (const float*)d_in[0];
    const float* encW = (const float*)d_in[1];
    const float* encb = (const float*)d_in[2];
    const float* decW = (const float*)d_in[3];
    const float* decb = (const float*)d_in[4];

    float* out = (float*)d_out;
    const long long B64  = (long long)BATCH * IN_DIM;
    const long long B512 = (long long)BATCH * LAT;

    float* ox = nullptr;
    float* oz = nullptr;
    if ((long long)out_size == B64 + B512) { ox = out; oz = out + B64; }
    else if ((long long)out_size == B512) { oz = out; }
    else if ((long long)out_size == B64)  { ox = out; }
    else { ox = out; oz = out + B64; }

    float* zstage = oz;
    if (!zstage) cudaGetSymbolAddress((void**)&zstage, g_scratch);
    float* xdst = ox;
    if (!xdst) cudaGetSymbolAddress((void**)&xdst, g_scratch);

    cudaFuncSetAttribute(sae_enc, cudaFuncAttributeMaxDynamicSharedMemorySize, K1_SMEM_BYTES);

    prep_transpose<<<(LAT * IN_DIM + 255) / 256, 256>>>(encW, decW);
    sae_enc<<<BATCH / 32, 256, K1_SMEM_BYTES>>>(x, encb, zstage);
    sae_topk<<<BATCH / 16, 128>>>(zstage, decb, xdst, zstage);
}